// round 3
// baseline (speedup 1.0000x reference)
#include <cuda_runtime.h>

#define SEQ    16384
#define CDIM   128
#define KDIM   64
#define BDIM   16
#define NCHUNK 16
#define STILE  128
#define TPB    256

// smem layout (floats): cw[64*128] | x_s[128*128] | x_t[128*130] | a_s[128*66] | sk[64] off[64] m2[64]
#define SMEM_FLOATS (KDIM*CDIM + STILE*CDIM + STILE*130 + STILE*66 + 3*64)
#define SMEM_BYTES  (SMEM_FLOATS * 4)

// deterministic scratch (no atomics)
__device__ float g_epart[(long)NCHUNK * BDIM * KDIM * CDIM];  // 2M floats
__device__ float g_Apart[NCHUNK * BDIM * KDIM];
__device__ float g_ecorr[BDIM * KDIM * CDIM];
__device__ float g_gk[KDIM];
__device__ float g_hk[KDIM];
__device__ float g_scale[BDIM * CDIM];

typedef unsigned long long u64;

__device__ __forceinline__ u64 pack2(float lo, float hi) {
    u64 r;
    asm("mov.b64 %0, {%1, %2};" : "=l"(r) : "r"(__float_as_int(lo)), "r"(__float_as_int(hi)));
    return r;
}
__device__ __forceinline__ void unpack2(u64 v, float& lo, float& hi) {
    int a, b;
    asm("mov.b64 {%0, %1}, %2;" : "=r"(a), "=r"(b) : "l"(v));
    lo = __int_as_float(a); hi = __int_as_float(b);
}
__device__ __forceinline__ void fma2(u64& d, u64 a, u64 b) {
    asm("fma.rn.f32x2 %0, %1, %2, %0;" : "+l"(d) : "l"(a), "l"(b));
}

// ---------------------------------------------------------------------------
// Kernel A: cross GEMM + softmax + aggregation GEMM, per (batch, seq-chunk)
// ---------------------------------------------------------------------------
__global__ void __launch_bounds__(TPB, 1) encnet_main(
    const float* __restrict__ x, const float* __restrict__ cw,
    const float* __restrict__ smth)
{
    extern __shared__ float smem[];
    float* cw_s  = smem;                       // [64][128]
    float* x_s   = cw_s + KDIM * CDIM;         // [c][s]  128x128
    float* x_t   = x_s + STILE * CDIM;         // [s][c]  128x130 (padded)
    float* a_s   = x_t + STILE * 130;          // [s][k]  128x66 (padded)
    float* sk_s  = a_s + STILE * 66;           // smoothing[k]
    float* off_s = sk_s + 64;                  // s_k * ||cw_k||^2
    float* m2_s  = off_s + 64;                 // -2 * s_k

    const int tid   = threadIdx.x;
    const int chunk = blockIdx.x;
    const int b     = blockIdx.y;

    // load codewords to smem (straight copy, coalesced)
    {
        const float4* src = reinterpret_cast<const float4*>(cw);
        float4* dst = reinterpret_cast<float4*>(cw_s);
        for (int i = tid; i < KDIM * CDIM / 4; i += TPB) dst[i] = __ldg(src + i);
    }
    // per-k constants straight from global (avoids smem row-stride conflicts)
    if (tid < KDIM) {
        const float4* row = reinterpret_cast<const float4*>(cw + tid * CDIM);
        float c2 = 0.f;
        #pragma unroll
        for (int j = 0; j < CDIM / 4; j++) {
            float4 v = __ldg(row + j);
            c2 += v.x * v.x + v.y * v.y + v.z * v.z + v.w * v.w;
        }
        float s = __ldg(smth + tid);
        sk_s[tid]  = s;
        off_s[tid] = s * c2;
        m2_s[tid]  = -2.f * s;
    }
    __syncthreads();

    // persistent aggregation accumulators: thread owns k-pair (2*kg,2*kg+1) x 16 c
    u64 eacc[16];
    #pragma unroll
    for (int i = 0; i < 16; i++) eacc[i] = 0ull;   // bits of (0.f, 0.f)
    float aA0 = 0.f, aA1 = 0.f;                    // sum_s a (k-pair), cg==0 only

    const int kg = tid & 31, cg = tid >> 5;
    const int warp = tid >> 5, lane = tid & 31;
    const int scross = tid & 127, kb = (tid >> 7) * 32;

    const float* xg = x + (long)b * CDIM * SEQ + chunk * (SEQ / NCHUNK);

    for (int t = 0; t < (SEQ / NCHUNK) / STILE; t++) {   // 8 tiles of 128 s
        // ---- load x tile into [c][s] layout: warp w owns rows w, w+8, ... ----
        const float* xt0 = xg + t * STILE;
        for (int cc = warp; cc < CDIM; cc += 8) {
            float4 v = __ldg(reinterpret_cast<const float4*>(xt0 + (long)cc * SEQ) + lane);
            *reinterpret_cast<float4*>(&x_s[cc * STILE + lane * 4]) = v;
        }
        __syncthreads();

        // ---- cross GEMM + logits: thread = (s, half-of-k) ----
        {
            u64 xr[64];
            float x2 = 0.f;
            #pragma unroll
            for (int j = 0; j < 64; j++) {
                float v0 = x_s[(2 * j) * STILE + scross];
                float v1 = x_s[(2 * j + 1) * STILE + scross];
                xr[j] = pack2(v0, v1);
                x2 = fmaf(v0, v0, x2);
                x2 = fmaf(v1, v1, x2);
            }
            // write transposed copy for the aggregation phase (half the threads)
            if (kb == 0) {
                u64* xtp = reinterpret_cast<u64*>(&x_t[scross * 130]);
                #pragma unroll
                for (int j = 0; j < 64; j++) xtp[j] = xr[j];
            }
            #pragma unroll 1
            for (int kk = 0; kk < 32; kk += 2) {
                const int k0 = kb + kk;
                const u64* c0p = reinterpret_cast<const u64*>(cw_s + k0 * CDIM);
                const u64* c1p = reinterpret_cast<const u64*>(cw_s + (k0 + 1) * CDIM);
                u64 a00 = 0ull, a01 = 0ull, a10 = 0ull, a11 = 0ull;
                #pragma unroll
                for (int j = 0; j < 64; j += 2) {
                    fma2(a00, xr[j],     c0p[j]);
                    fma2(a10, xr[j],     c1p[j]);
                    fma2(a01, xr[j + 1], c0p[j + 1]);
                    fma2(a11, xr[j + 1], c1p[j + 1]);
                }
                float p0, q0, p1, q1;
                unpack2(a00, p0, q0); unpack2(a01, p1, q1);
                float cr0 = (p0 + q0) + (p1 + q1);
                unpack2(a10, p0, q0); unpack2(a11, p1, q1);
                float cr1 = (p0 + q0) + (p1 + q1);
                a_s[scross * 66 + k0]     = fmaf(m2_s[k0],     cr0, fmaf(sk_s[k0],     x2, off_s[k0]));
                a_s[scross * 66 + k0 + 1] = fmaf(m2_s[k0 + 1], cr1, fmaf(sk_s[k0 + 1], x2, off_s[k0 + 1]));
            }
        }
        __syncthreads();

        // ---- softmax over k (one thread per s) ----
        if (tid < STILE) {
            float2 l[32];
            float m = -3.4e38f;
            #pragma unroll
            for (int j = 0; j < 32; j++) {
                l[j] = *reinterpret_cast<const float2*>(&a_s[tid * 66 + 2 * j]);
                m = fmaxf(m, fmaxf(l[j].x, l[j].y));
            }
            float sum = 0.f;
            #pragma unroll
            for (int j = 0; j < 32; j++) {
                l[j].x = __expf(l[j].x - m);
                l[j].y = __expf(l[j].y - m);
                sum += l[j].x + l[j].y;
            }
            float inv = 1.f / sum;
            #pragma unroll
            for (int j = 0; j < 32; j++) {
                l[j].x *= inv; l[j].y *= inv;
                *reinterpret_cast<float2*>(&a_s[tid * 66 + 2 * j]) = l[j];
            }
        }
        __syncthreads();

        // ---- aggregation GEMM: thread = (k-pair kg, c-group cg) ----
        {
            const int c0 = cg * 16;
            for (int s = 0; s < STILE; s++) {
                float2 av = *reinterpret_cast<const float2*>(&a_s[s * 66 + 2 * kg]);
                if (cg == 0) { aA0 += av.x; aA1 += av.y; }
                u64 ax = pack2(av.x, av.x);
                u64 ay = pack2(av.y, av.y);
                const u64* xp = reinterpret_cast<const u64*>(&x_t[s * 130 + c0]);
                #pragma unroll
                for (int j = 0; j < 8; j++) {
                    fma2(eacc[j],     ax, xp[j]);
                    fma2(eacc[8 + j], ay, xp[j]);
                }
            }
        }
        __syncthreads();
    }

    // ---- write deterministic chunk partials ----
    {
        float* ep = g_epart + ((long)(chunk * BDIM + b) * KDIM) * CDIM;
        const int k0 = 2 * kg, c0 = cg * 16;
        #pragma unroll
        for (int j = 0; j < 8; j++) {
            float lo, hi;
            unpack2(eacc[j], lo, hi);
            *reinterpret_cast<float2*>(&ep[k0 * CDIM + c0 + 2 * j]) = make_float2(lo, hi);
            unpack2(eacc[8 + j], lo, hi);
            *reinterpret_cast<float2*>(&ep[(k0 + 1) * CDIM + c0 + 2 * j]) = make_float2(lo, hi);
        }
        if (cg == 0) {
            g_Apart[(chunk * BDIM + b) * KDIM + k0]     = aA0;
            g_Apart[(chunk * BDIM + b) * KDIM + k0 + 1] = aA1;
        }
    }
}

// ---------------------------------------------------------------------------
// Kernel B: reduce chunk partials, subtract A*cw, BN batch stats per k
// ---------------------------------------------------------------------------
__global__ void encnet_stats(const float* __restrict__ cw,
                             const float* __restrict__ bnw,
                             const float* __restrict__ bnb)
{
    const int k = blockIdx.x, tid = threadIdx.x;
    __shared__ float Ab[BDIM];
    __shared__ float red[TPB];

    if (tid < BDIM) {
        float a = 0.f;
        #pragma unroll
        for (int ch = 0; ch < NCHUNK; ch++) a += g_Apart[(ch * BDIM + tid) * KDIM + k];
        Ab[tid] = a;
    }
    __syncthreads();

    float sum = 0.f, ss = 0.f;
    for (int i = tid; i < BDIM * CDIM; i += TPB) {
        int bb = i >> 7, c = i & 127;
        float v = 0.f;
        #pragma unroll
        for (int ch = 0; ch < NCHUNK; ch++)
            v += g_epart[(((long)ch * BDIM + bb) * KDIM + k) * CDIM + c];
        v -= Ab[bb] * __ldg(cw + k * CDIM + c);
        g_ecorr[(bb * KDIM + k) * CDIM + c] = v;
        sum += v;
        ss = fmaf(v, v, ss);
    }
    red[tid] = sum; __syncthreads();
    for (int o = TPB / 2; o > 0; o >>= 1) { if (tid < o) red[tid] += red[tid + o]; __syncthreads(); }
    float tsum = red[0]; __syncthreads();
    red[tid] = ss; __syncthreads();
    for (int o = TPB / 2; o > 0; o >>= 1) { if (tid < o) red[tid] += red[tid + o]; __syncthreads(); }
    if (tid == 0) {
        const float n = (float)(BDIM * CDIM);
        float mean = tsum / n;
        float var = red[0] / n - mean * mean;
        float rstd = rsqrtf(var + 1e-5f);
        float g = rstd * __ldg(bnw + k);
        g_gk[k] = g;
        g_hk[k] = __ldg(bnb + k) - mean * g;
    }
}

// ---------------------------------------------------------------------------
// Kernel C: e_norm (mean of relu over k) + FC + sigmoid -> per-(b,c) scale
// ---------------------------------------------------------------------------
__global__ void encnet_fc(const float* __restrict__ fcw, const float* __restrict__ fcb)
{
    const int b = blockIdx.x, tid = threadIdx.x;   // 128 threads
    __shared__ float en[CDIM];
    float acc = 0.f;
    #pragma unroll 4
    for (int k = 0; k < KDIM; k++) {
        float v = g_ecorr[(b * KDIM + k) * CDIM + tid];
        acc += fmaxf(fmaf(v, g_gk[k], g_hk[k]), 0.f);
    }
    en[tid] = acc * (1.f / (float)KDIM);
    __syncthreads();

    float lg = __ldg(fcb + tid);
    const float* wr = fcw + tid * CDIM;
    #pragma unroll 4
    for (int c2 = 0; c2 < CDIM; c2++) lg = fmaf(en[c2], __ldg(wr + c2), lg);
    g_scale[b * CDIM + tid] = 1.f / (1.f + __expf(-lg));
}

// ---------------------------------------------------------------------------
// Kernel D: out = x * scale  (memory bound)
// ---------------------------------------------------------------------------
__global__ void encnet_scale(const float4* __restrict__ x4, float4* __restrict__ out4)
{
    const int total = (BDIM * CDIM * SEQ) / 4;   // 8388608 float4
    for (int i = blockIdx.x * blockDim.x + threadIdx.x; i < total;
         i += gridDim.x * blockDim.x) {
        float s = __ldg(&g_scale[i >> 12]);      // 4096 float4 per (b,c)
        float4 v = __ldg(x4 + i);
        v.x *= s; v.y *= s; v.z *= s; v.w *= s;
        out4[i] = v;
    }
}

// ---------------------------------------------------------------------------
extern "C" void kernel_launch(void* const* d_in, const int* in_sizes, int n_in,
                              void* d_out, int out_size)
{
    const float* x    = (const float*)d_in[0];
    const float* cw   = (const float*)d_in[1];
    const float* smth = (const float*)d_in[2];
    const float* bnw  = (const float*)d_in[3];
    const float* bnb  = (const float*)d_in[4];
    const float* fcw  = (const float*)d_in[5];
    const float* fcb  = (const float*)d_in[6];
    float* out = (float*)d_out;

    cudaFuncSetAttribute(encnet_main, cudaFuncAttributeMaxDynamicSharedMemorySize, SMEM_BYTES);

    encnet_main <<<dim3(NCHUNK, BDIM), TPB, SMEM_BYTES>>>(x, cw, smth);
    encnet_stats<<<KDIM, TPB>>>(cw, bnw, bnb);
    encnet_fc   <<<BDIM, CDIM>>>(fcw, fcb);
    encnet_scale<<<4096, 256>>>((const float4*)x, (float4*)out);
}

// round 4
// speedup vs baseline: 1.0325x; 1.0325x over previous
#include <cuda_runtime.h>

#define SEQ    16384
#define CDIM   128
#define KDIM   64
#define BDIM   16
#define NCHUNK 16
#define STILE  128
#define TPB    256
#define NTILE  ((SEQ / NCHUNK) / STILE)   // 8

// smem layout (floats): cw[64*128] | x_s[128*128] | x_t[128*130] | a_s[128*66] | sk/off/m2[64 each]
#define XT_STRIDE 130
#define AS_STRIDE 66
#define SMEM_FLOATS (KDIM*CDIM + STILE*CDIM + STILE*XT_STRIDE + STILE*AS_STRIDE + 3*64)
#define SMEM_BYTES  (SMEM_FLOATS * 4)

// deterministic scratch (no atomics)
__device__ float g_epart[(long)NCHUNK * BDIM * KDIM * CDIM];  // 2M floats
__device__ float g_Apart[NCHUNK * BDIM * KDIM];
__device__ float g_ecorr[BDIM * KDIM * CDIM];
__device__ float g_gk[KDIM];
__device__ float g_hk[KDIM];
__device__ float g_scale[BDIM * CDIM];

typedef unsigned long long u64;

__device__ __forceinline__ u64 pack2(float lo, float hi) {
    u64 r;
    asm("mov.b64 %0, {%1, %2};" : "=l"(r) : "r"(__float_as_int(lo)), "r"(__float_as_int(hi)));
    return r;
}
__device__ __forceinline__ void unpack2(u64 v, float& lo, float& hi) {
    int a, b;
    asm("mov.b64 {%0, %1}, %2;" : "=r"(a), "=r"(b) : "l"(v));
    lo = __int_as_float(a); hi = __int_as_float(b);
}
__device__ __forceinline__ void fma2(u64& d, u64 a, u64 b) {
    asm("fma.rn.f32x2 %0, %1, %2, %0;" : "+l"(d) : "l"(a), "l"(b));
}
__device__ __forceinline__ unsigned smem_u32(const void* p) {
    unsigned a;
    asm("{ .reg .u64 t; cvta.to.shared.u64 t, %1; cvt.u32.u64 %0, t; }" : "=r"(a) : "l"(p));
    return a;
}
__device__ __forceinline__ void cp_async16(unsigned dst, const float* src) {
    asm volatile("cp.async.cg.shared.global [%0], [%1], 16;" :: "r"(dst), "l"(src));
}
__device__ __forceinline__ void cp_commit() { asm volatile("cp.async.commit_group;"); }
__device__ __forceinline__ void cp_wait0()  { asm volatile("cp.async.wait_group 0;" ::: "memory"); }

// ---------------------------------------------------------------------------
// Kernel A: cross GEMM + softmax + aggregation GEMM, per (batch, seq-chunk)
// ---------------------------------------------------------------------------
__global__ void __launch_bounds__(TPB, 1) encnet_main(
    const float* __restrict__ x, const float* __restrict__ cw,
    const float* __restrict__ smth)
{
    extern __shared__ float smem[];
    float* cw_s  = smem;                            // [64][128]
    float* x_s   = cw_s + KDIM * CDIM;              // [c][s]  128x128 (cp.async staged)
    float* x_t   = x_s + STILE * CDIM;              // [s][c]  128x130 (padded)
    float* a_s   = x_t + STILE * XT_STRIDE;         // [s][k]  128x66  (padded)
    float* sk_s  = a_s + STILE * AS_STRIDE;
    float* off_s = sk_s + 64;
    float* m2_s  = off_s + 64;

    const int tid   = threadIdx.x;
    const int chunk = blockIdx.x;
    const int b     = blockIdx.y;

    // codewords -> smem (coalesced)
    {
        const float4* src = reinterpret_cast<const float4*>(cw);
        float4* dst = reinterpret_cast<float4*>(cw_s);
        for (int i = tid; i < KDIM * CDIM / 4; i += TPB) dst[i] = __ldg(src + i);
    }
    // per-k logit constants
    if (tid < KDIM) {
        const float4* row = reinterpret_cast<const float4*>(cw + tid * CDIM);
        float c2 = 0.f;
        #pragma unroll
        for (int j = 0; j < CDIM / 4; j++) {
            float4 v = __ldg(row + j);
            c2 += v.x * v.x + v.y * v.y + v.z * v.z + v.w * v.w;
        }
        float s = __ldg(smth + tid);
        sk_s[tid]  = s;
        off_s[tid] = s * c2;
        m2_s[tid]  = -2.f * s;
    }

    const int warp = tid >> 5, lane = tid & 31;
    const int scross = tid & 127, kb = (tid >> 7) * 32;
    const int kbase = 8 * warp;                      // agg: warp owns k = kbase..kbase+7

    const float* xg = x + (long)b * CDIM * SEQ + chunk * (SEQ / NCHUNK);
    const unsigned xs_base = smem_u32(x_s);

    // persistent accumulators: eacc[p*4+m] = (e[kbase+2p][lane+32m], e[kbase+2p+1][lane+32m])
    u64 eacc[16];
    #pragma unroll
    for (int i = 0; i < 16; i++) eacc[i] = 0ull;
    float aAcc = 0.f;                                // tid<64: sum_s a[., tid]

    // prefetch tile 0 into x_s: 128 rows x 32 x 16B segments
    #pragma unroll
    for (int it = 0; it < 16; it++) {
        int idx = tid + it * TPB;                    // 0..4095
        int cc = idx >> 5, seg = idx & 31;
        cp_async16(xs_base + (unsigned)(cc * STILE + seg * 4) * 4u,
                   xg + (long)cc * SEQ + seg * 4);
    }
    cp_commit();

    for (int t = 0; t < NTILE; t++) {
        cp_wait0();
        __syncthreads();   // x_s ready for all; previous tile's a_s/x_t consumers done

        // ---- cross GEMM + logits: thread = (s, half-of-k) ----
        {
            u64 xr[64];
            float x2 = 0.f;
            #pragma unroll
            for (int j = 0; j < 64; j++) {
                float v0 = x_s[(2 * j) * STILE + scross];
                float v1 = x_s[(2 * j + 1) * STILE + scross];
                xr[j] = pack2(v0, v1);
                x2 = fmaf(v0, v0, x2);
                x2 = fmaf(v1, v1, x2);
            }
            // transposed copy for the aggregation phase (half the threads)
            if (kb == 0) {
                u64* xtp = reinterpret_cast<u64*>(&x_t[scross * XT_STRIDE]);
                #pragma unroll
                for (int j = 0; j < 64; j++) xtp[j] = xr[j];
            }
            #pragma unroll 1
            for (int kk = 0; kk < 32; kk += 2) {
                const int k0 = kb + kk;
                const float4* c0p = reinterpret_cast<const float4*>(cw_s + k0 * CDIM);
                const float4* c1p = c0p + 32;
                u64 a00 = 0ull, a01 = 0ull, a10 = 0ull, a11 = 0ull;
                #pragma unroll
                for (int j = 0; j < 32; j++) {
                    float4 q0 = c0p[j];
                    float4 q1 = c1p[j];
                    u64 q0lo = pack2(q0.x, q0.y), q0hi = pack2(q0.z, q0.w);
                    u64 q1lo = pack2(q1.x, q1.y), q1hi = pack2(q1.z, q1.w);
                    fma2(a00, xr[2 * j],     q0lo);
                    fma2(a10, xr[2 * j],     q1lo);
                    fma2(a01, xr[2 * j + 1], q0hi);
                    fma2(a11, xr[2 * j + 1], q1hi);
                }
                float p0, q0, p1, q1;
                unpack2(a00, p0, q0); unpack2(a01, p1, q1);
                float cr0 = (p0 + q0) + (p1 + q1);
                unpack2(a10, p0, q0); unpack2(a11, p1, q1);
                float cr1 = (p0 + q0) + (p1 + q1);
                a_s[scross * AS_STRIDE + k0]     = fmaf(m2_s[k0],     cr0, fmaf(sk_s[k0],     x2, off_s[k0]));
                a_s[scross * AS_STRIDE + k0 + 1] = fmaf(m2_s[k0 + 1], cr1, fmaf(sk_s[k0 + 1], x2, off_s[k0 + 1]));
            }
        }
        __syncthreads();   // x_s reads done; a_s/x_t written

        // prefetch next tile (overlaps softmax + aggregation)
        if (t + 1 < NTILE) {
            const float* xt1 = xg + (t + 1) * STILE;
            #pragma unroll
            for (int it = 0; it < 16; it++) {
                int idx = tid + it * TPB;
                int cc = idx >> 5, seg = idx & 31;
                cp_async16(xs_base + (unsigned)(cc * STILE + seg * 4) * 4u,
                           xt1 + (long)cc * SEQ + seg * 4);
            }
        }
        cp_commit();

        // ---- softmax over k (one thread per s) ----
        if (tid < STILE) {
            float2 l[32];
            float m = -3.4e38f;
            #pragma unroll
            for (int j = 0; j < 32; j++) {
                l[j] = *reinterpret_cast<const float2*>(&a_s[tid * AS_STRIDE + 2 * j]);
                m = fmaxf(m, fmaxf(l[j].x, l[j].y));
            }
            float sum = 0.f;
            #pragma unroll
            for (int j = 0; j < 32; j++) {
                l[j].x = __expf(l[j].x - m);
                l[j].y = __expf(l[j].y - m);
                sum += l[j].x + l[j].y;
            }
            float inv = 1.f / sum;
            #pragma unroll
            for (int j = 0; j < 32; j++) {
                l[j].x *= inv; l[j].y *= inv;
                *reinterpret_cast<float2*>(&a_s[tid * AS_STRIDE + 2 * j]) = l[j];
            }
        }
        __syncthreads();

        // ---- aggregation GEMM: warp owns 8 k (broadcast a), lane owns 4 strided c ----
        {
            #pragma unroll 2
            for (int s = 0; s < STILE; s++) {
                const float* ar = a_s + s * AS_STRIDE + kbase;
                u64 ap0 = *reinterpret_cast<const u64*>(ar);
                u64 ap1 = *reinterpret_cast<const u64*>(ar + 2);
                u64 ap2 = *reinterpret_cast<const u64*>(ar + 4);
                u64 ap3 = *reinterpret_cast<const u64*>(ar + 6);
                const float* xrow = x_t + s * XT_STRIDE + lane;
                u64 xs0 = pack2(xrow[0],  xrow[0]);
                u64 xs1 = pack2(xrow[32], xrow[32]);
                u64 xs2 = pack2(xrow[64], xrow[64]);
                u64 xs3 = pack2(xrow[96], xrow[96]);
                fma2(eacc[0],  ap0, xs0); fma2(eacc[1],  ap0, xs1);
                fma2(eacc[2],  ap0, xs2); fma2(eacc[3],  ap0, xs3);
                fma2(eacc[4],  ap1, xs0); fma2(eacc[5],  ap1, xs1);
                fma2(eacc[6],  ap1, xs2); fma2(eacc[7],  ap1, xs3);
                fma2(eacc[8],  ap2, xs0); fma2(eacc[9],  ap2, xs1);
                fma2(eacc[10], ap2, xs2); fma2(eacc[11], ap2, xs3);
                fma2(eacc[12], ap3, xs0); fma2(eacc[13], ap3, xs1);
                fma2(eacc[14], ap3, xs2); fma2(eacc[15], ap3, xs3);
            }
        }

        // ---- per-k sum of a over this tile (cheap, conflict-free) ----
        if (tid < KDIM) {
            #pragma unroll 8
            for (int s = 0; s < STILE; s++) aAcc += a_s[s * AS_STRIDE + tid];
        }
        // NOTE: no sync here; top-of-loop sync (after cp_wait0) orders a_s/x_t rewrite
        __syncthreads();
    }

    // ---- write deterministic chunk partials ----
    {
        float* ep = g_epart + ((long)(chunk * BDIM + b) * KDIM) * CDIM;
        #pragma unroll
        for (int p = 0; p < 4; p++) {
            #pragma unroll
            for (int m = 0; m < 4; m++) {
                float lo, hi;
                unpack2(eacc[p * 4 + m], lo, hi);
                ep[(kbase + 2 * p)     * CDIM + lane + 32 * m] = lo;
                ep[(kbase + 2 * p + 1) * CDIM + lane + 32 * m] = hi;
            }
        }
        if (tid < KDIM) g_Apart[(chunk * BDIM + b) * KDIM + tid] = aAcc;
    }
}

// ---------------------------------------------------------------------------
// Kernel B: reduce chunk partials, subtract A*cw, BN batch stats per k
// ---------------------------------------------------------------------------
__global__ void encnet_stats(const float* __restrict__ cw,
                             const float* __restrict__ bnw,
                             const float* __restrict__ bnb)
{
    const int k = blockIdx.x, tid = threadIdx.x;
    __shared__ float Ab[BDIM];
    __shared__ float red[TPB];

    if (tid < BDIM) {
        float a = 0.f;
        #pragma unroll
        for (int ch = 0; ch < NCHUNK; ch++) a += g_Apart[(ch * BDIM + tid) * KDIM + k];
        Ab[tid] = a;
    }
    __syncthreads();

    float sum = 0.f, ss = 0.f;
    for (int i = tid; i < BDIM * CDIM; i += TPB) {
        int bb = i >> 7, c = i & 127;
        float v = 0.f;
        #pragma unroll
        for (int ch = 0; ch < NCHUNK; ch++)
            v += g_epart[(((long)ch * BDIM + bb) * KDIM + k) * CDIM + c];
        v -= Ab[bb] * __ldg(cw + k * CDIM + c);
        g_ecorr[(bb * KDIM + k) * CDIM + c] = v;
        sum += v;
        ss = fmaf(v, v, ss);
    }
    red[tid] = sum; __syncthreads();
    for (int o = TPB / 2; o > 0; o >>= 1) { if (tid < o) red[tid] += red[tid + o]; __syncthreads(); }
    float tsum = red[0]; __syncthreads();
    red[tid] = ss; __syncthreads();
    for (int o = TPB / 2; o > 0; o >>= 1) { if (tid < o) red[tid] += red[tid + o]; __syncthreads(); }
    if (tid == 0) {
        const float n = (float)(BDIM * CDIM);
        float mean = tsum / n;
        float var = red[0] / n - mean * mean;
        float rstd = rsqrtf(var + 1e-5f);
        float g = rstd * __ldg(bnw + k);
        g_gk[k] = g;
        g_hk[k] = __ldg(bnb + k) - mean * g;
    }
}

// ---------------------------------------------------------------------------
// Kernel C: e_norm (mean of relu over k) + FC + sigmoid -> per-(b,c) scale
// ---------------------------------------------------------------------------
__global__ void encnet_fc(const float* __restrict__ fcw, const float* __restrict__ fcb)
{
    const int b = blockIdx.x, tid = threadIdx.x;   // 128 threads
    __shared__ float en[CDIM];
    float acc = 0.f;
    #pragma unroll 4
    for (int k = 0; k < KDIM; k++) {
        float v = g_ecorr[(b * KDIM + k) * CDIM + tid];
        acc += fmaxf(fmaf(v, g_gk[k], g_hk[k]), 0.f);
    }
    en[tid] = acc * (1.f / (float)KDIM);
    __syncthreads();

    float lg = __ldg(fcb + tid);
    const float* wr = fcw + tid * CDIM;
    #pragma unroll 4
    for (int c2 = 0; c2 < CDIM; c2++) lg = fmaf(en[c2], __ldg(wr + c2), lg);
    g_scale[b * CDIM + tid] = 1.f / (1.f + __expf(-lg));
}

// ---------------------------------------------------------------------------
// Kernel D: out = x * scale  (memory bound)
// ---------------------------------------------------------------------------
__global__ void encnet_scale(const float4* __restrict__ x4, float4* __restrict__ out4)
{
    const int total = (BDIM * CDIM * SEQ) / 4;   // 8388608 float4
    for (int i = blockIdx.x * blockDim.x + threadIdx.x; i < total;
         i += gridDim.x * blockDim.x) {
        float s = __ldg(&g_scale[i >> 12]);      // 4096 float4 per (b,c)
        float4 v = __ldg(x4 + i);
        v.x *= s; v.y *= s; v.z *= s; v.w *= s;
        out4[i] = v;
    }
}

// ---------------------------------------------------------------------------
extern "C" void kernel_launch(void* const* d_in, const int* in_sizes, int n_in,
                              void* d_out, int out_size)
{
    const float* x    = (const float*)d_in[0];
    const float* cw   = (const float*)d_in[1];
    const float* smth = (const float*)d_in[2];
    const float* bnw  = (const float*)d_in[3];
    const float* bnb  = (const float*)d_in[4];
    const float* fcw  = (const float*)d_in[5];
    const float* fcb  = (const float*)d_in[6];
    float* out = (float*)d_out;

    cudaFuncSetAttribute(encnet_main, cudaFuncAttributeMaxDynamicSharedMemorySize, SMEM_BYTES);

    encnet_main <<<dim3(NCHUNK, BDIM), TPB, SMEM_BYTES>>>(x, cw, smth);
    encnet_stats<<<KDIM, TPB>>>(cw, bnw, bnb);
    encnet_fc   <<<BDIM, CDIM>>>(fcw, fcb);
    encnet_scale<<<4096, 256>>>((const float4*)x, (float4*)out);
}